// round 1
// baseline (speedup 1.0000x reference)
#include <cuda_runtime.h>
#include <cstddef>

#define NEGV -1000000000.0f
#define HDIM 128

__global__ void fill_kernel(float4* __restrict__ out, int n4) {
    int i = blockIdx.x * blockDim.x + threadIdx.x;
    if (i < n4) {
        out[i] = make_float4(NEGV, NEGV, NEGV, NEGV);
    }
}

__global__ void edge_kernel(const float* __restrict__ h,
                            const int* __restrict__ sources,
                            const int* __restrict__ dests,
                            const float* __restrict__ weights,
                            const float* __restrict__ W,
                            const float* __restrict__ b,
                            float* __restrict__ out,
                            int E, int N) {
    __shared__ __align__(16) float sW[260]; // [0:128) dest-W, [128:256) src-W, [256] wW, [257] b
    for (int i = threadIdx.x; i < 258; i += blockDim.x) {
        sW[i] = (i < 257) ? W[i] : b[0];
    }
    __syncthreads();

    int warp = (blockIdx.x * blockDim.x + threadIdx.x) >> 5;
    int lane = threadIdx.x & 31;
    if (warp >= E) return;

    int s = sources[warp];
    int d = dests[warp];

    const float4 hd = *reinterpret_cast<const float4*>(h + (size_t)d * HDIM + lane * 4);
    const float4 hs = *reinterpret_cast<const float4*>(h + (size_t)s * HDIM + lane * 4);
    const float4 wd = *reinterpret_cast<const float4*>(sW + lane * 4);
    const float4 ws = *reinterpret_cast<const float4*>(sW + HDIM + lane * 4);

    float acc = hd.x * wd.x + hd.y * wd.y + hd.z * wd.z + hd.w * wd.w
              + hs.x * ws.x + hs.y * ws.y + hs.z * ws.z + hs.w * ws.w;

    #pragma unroll
    for (int o = 16; o; o >>= 1)
        acc += __shfl_xor_sync(0xffffffffu, acc, o);

    if (lane == 0) {
        float val = acc + weights[warp] * sW[256] + sW[257];
        out[(size_t)d * N + s] = val;
    }
}

extern "C" void kernel_launch(void* const* d_in, const int* in_sizes, int n_in,
                              void* d_out, int out_size) {
    const float* h       = (const float*)d_in[0];
    const int*   sources = (const int*)d_in[1];
    const int*   dests   = (const int*)d_in[2];
    const float* weights = (const float*)d_in[3];
    const float* W       = (const float*)d_in[4];
    const float* b       = (const float*)d_in[5];
    float* out = (float*)d_out;

    const int N = in_sizes[0] / HDIM;     // 12288
    const int E = in_sizes[1];            // 393216

    // Pass 1: fill scores with NEG (vectorized float4 stores)
    long long total = (long long)N * N;
    int n4 = (int)(total >> 2);
    int threads = 256;
    int blocks = (n4 + threads - 1) / threads;
    fill_kernel<<<blocks, threads>>>((float4*)out, n4);

    // Pass 2: one warp per edge — compute score and scatter
    const int warps_per_block = 8; // 256 threads
    int eblocks = (E + warps_per_block - 1) / warps_per_block;
    edge_kernel<<<eblocks, warps_per_block * 32>>>(h, sources, dests, weights,
                                                   W, b, out, E, N);
}

// round 2
// speedup vs baseline: 1.1108x; 1.1108x over previous
#include <cuda_runtime.h>
#include <cstddef>

#define NEGV -1000000000.0f
#define HDIM 128
#define EMAX 393216

// scratch for per-edge scores (allocation-free rule -> device global)
__device__ float g_vals[EMAX];

__global__ void fill_kernel(float4* __restrict__ out, int n4) {
    int i = blockIdx.x * blockDim.x + threadIdx.x;
    if (i < n4) {
        out[i] = make_float4(NEGV, NEGV, NEGV, NEGV);
    }
}

// 16 lanes per edge, 2 edges per warp, grid-stride. W in registers.
__global__ void vals_kernel(const float* __restrict__ h,
                            const int* __restrict__ sources,
                            const int* __restrict__ dests,
                            const float* __restrict__ weights,
                            const float* __restrict__ W,
                            const float* __restrict__ b,
                            int E) {
    const int lane = threadIdx.x & 31;
    const int sub  = lane & 15;   // lane within the 16-lane group
    const int half = lane >> 4;   // which edge of the pair
    const int warp_global = (blockIdx.x * blockDim.x + threadIdx.x) >> 5;
    const int nwarps      = (gridDim.x * blockDim.x) >> 5;

    // Per-lane slice of W: dest part W[0:128), source part W[128:256)
    const float4 wd0 = *reinterpret_cast<const float4*>(W + sub * 8);
    const float4 wd1 = *reinterpret_cast<const float4*>(W + sub * 8 + 4);
    const float4 ws0 = *reinterpret_cast<const float4*>(W + HDIM + sub * 8);
    const float4 ws1 = *reinterpret_cast<const float4*>(W + HDIM + sub * 8 + 4);
    const float  wW  = W[2 * HDIM];
    const float  bb  = b[0];

    for (int e0 = warp_global * 2; e0 < E; e0 += nwarps * 2) {
        const int e = e0 + half;
        float acc = 0.0f;
        int s = 0, d = 0;
        if (e < E) {
            s = sources[e];
            d = dests[e];
            const float* hd = h + (size_t)d * HDIM + sub * 8;
            const float* hs = h + (size_t)s * HDIM + sub * 8;
            const float4 a0 = *reinterpret_cast<const float4*>(hd);
            const float4 a1 = *reinterpret_cast<const float4*>(hd + 4);
            const float4 c0 = *reinterpret_cast<const float4*>(hs);
            const float4 c1 = *reinterpret_cast<const float4*>(hs + 4);
            acc = a0.x * wd0.x + a0.y * wd0.y + a0.z * wd0.z + a0.w * wd0.w
                + a1.x * wd1.x + a1.y * wd1.y + a1.z * wd1.z + a1.w * wd1.w
                + c0.x * ws0.x + c0.y * ws0.y + c0.z * ws0.z + c0.w * ws0.w
                + c1.x * ws1.x + c1.y * ws1.y + c1.z * ws1.z + c1.w * ws1.w;
        }
        // reduce within each 16-lane group (xor offsets stay inside the group)
        #pragma unroll
        for (int o = 8; o; o >>= 1)
            acc += __shfl_xor_sync(0xffffffffu, acc, o);

        if (sub == 0 && e < E) {
            g_vals[e] = acc + weights[e] * wW + bb;
        }
    }
}

__global__ void scatter_kernel(const int* __restrict__ sources,
                               const int* __restrict__ dests,
                               float* __restrict__ out, int E, int N) {
    int e = blockIdx.x * blockDim.x + threadIdx.x;
    if (e < E) {
        out[(size_t)dests[e] * N + sources[e]] = g_vals[e];
    }
}

extern "C" void kernel_launch(void* const* d_in, const int* in_sizes, int n_in,
                              void* d_out, int out_size) {
    const float* h       = (const float*)d_in[0];
    const int*   sources = (const int*)d_in[1];
    const int*   dests   = (const int*)d_in[2];
    const float* weights = (const float*)d_in[3];
    const float* W       = (const float*)d_in[4];
    const float* b       = (const float*)d_in[5];
    float* out = (float*)d_out;

    const int N = in_sizes[0] / HDIM;     // 12288
    const int E = in_sizes[1];            // 393216

    // One-time side stream + events for fork-join overlap (created on the
    // first, uncaptured correctness call; reused identically every call).
    static cudaStream_t s_side = nullptr;
    static cudaEvent_t  s_fork = nullptr, s_join = nullptr;
    static bool s_init = false;
    if (!s_init) {
        s_init = true;
        if (cudaStreamCreateWithFlags(&s_side, cudaStreamNonBlocking) != cudaSuccess)
            s_side = nullptr;
        if (s_side) {
            if (cudaEventCreateWithFlags(&s_fork, cudaEventDisableTiming) != cudaSuccess ||
                cudaEventCreateWithFlags(&s_join, cudaEventDisableTiming) != cudaSuccess) {
                s_side = nullptr;
            }
        }
    }

    long long total = (long long)N * N;
    int n4 = (int)(total >> 2);
    const int fill_threads = 256;
    int fill_blocks = (n4 + fill_threads - 1) / fill_threads;

    const int vals_blocks = 1184;  // 8 CTAs/SM on 148 SMs, grid-stride
    const int vals_threads = 256;

    const int sc_threads = 256;
    int sc_blocks = (E + sc_threads - 1) / sc_threads;

    if (s_side) {
        // fork: vals on side stream, fill on main stream, join before scatter
        cudaEventRecord(s_fork, 0);
        cudaStreamWaitEvent(s_side, s_fork, 0);
        vals_kernel<<<vals_blocks, vals_threads, 0, s_side>>>(
            h, sources, dests, weights, W, b, E);
        cudaEventRecord(s_join, s_side);

        fill_kernel<<<fill_blocks, fill_threads>>>((float4*)out, n4);

        cudaStreamWaitEvent(0, s_join, 0);
        scatter_kernel<<<sc_blocks, sc_threads>>>(sources, dests, out, E, N);
    } else {
        // fallback: sequential on the main stream
        vals_kernel<<<vals_blocks, vals_threads>>>(h, sources, dests, weights, W, b, E);
        fill_kernel<<<fill_blocks, fill_threads>>>((float4*)out, n4);
        scatter_kernel<<<sc_blocks, sc_threads>>>(sources, dests, out, E, N);
    }
}

// round 3
// speedup vs baseline: 1.5467x; 1.3924x over previous
#include <cuda_runtime.h>
#include <cstddef>

#define NEGV -1000000000.0f
#define HDIM 128
#define NMAX 12288

// per-node partials: g_p[n].x = h[n] . W[0:128]  (dest part)
//                    g_p[n].y = h[n] . W[128:256] (src part)
__device__ float2 g_p[NMAX];

// One warp per node: dual dot product with butterfly reduction.
__global__ void node_partials(const float* __restrict__ h,
                              const float* __restrict__ W,
                              int N) {
    int warp = (blockIdx.x * blockDim.x + threadIdx.x) >> 5;
    int lane = threadIdx.x & 31;
    if (warp >= N) return;

    const float4 hv = *reinterpret_cast<const float4*>(h + (size_t)warp * HDIM + lane * 4);
    const float4 wd = *reinterpret_cast<const float4*>(W + lane * 4);
    const float4 ws = *reinterpret_cast<const float4*>(W + HDIM + lane * 4);

    float ad = hv.x * wd.x + hv.y * wd.y + hv.z * wd.z + hv.w * wd.w;
    float as = hv.x * ws.x + hv.y * ws.y + hv.z * ws.z + hv.w * ws.w;

    #pragma unroll
    for (int o = 16; o; o >>= 1) {
        ad += __shfl_xor_sync(0xffffffffu, ad, o);
        as += __shfl_xor_sync(0xffffffffu, as, o);
    }
    if (lane == 0) {
        g_p[warp] = make_float2(ad, as);
    }
}

__global__ void fill_kernel(float4* __restrict__ out, int n4) {
    int i = blockIdx.x * blockDim.x + threadIdx.x;
    if (i < n4) {
        out[i] = make_float4(NEGV, NEGV, NEGV, NEGV);
    }
}

// Per edge: two 8-byte L2-resident gathers + one scattered 4B store.
__global__ void scatter_kernel(const int* __restrict__ sources,
                               const int* __restrict__ dests,
                               const float* __restrict__ weights,
                               const float* __restrict__ W,
                               const float* __restrict__ b,
                               float* __restrict__ out, int E, int N) {
    int e = blockIdx.x * blockDim.x + threadIdx.x;
    if (e >= E) return;
    int s = sources[e];
    int d = dests[e];
    float val = g_p[d].x + g_p[s].y + weights[e] * W[2 * HDIM] + b[0];
    out[(size_t)d * N + s] = val;
}

extern "C" void kernel_launch(void* const* d_in, const int* in_sizes, int n_in,
                              void* d_out, int out_size) {
    const float* h       = (const float*)d_in[0];
    const int*   sources = (const int*)d_in[1];
    const int*   dests   = (const int*)d_in[2];
    const float* weights = (const float*)d_in[3];
    const float* W       = (const float*)d_in[4];
    const float* b       = (const float*)d_in[5];
    float* out = (float*)d_out;

    const int N = in_sizes[0] / HDIM;     // 12288
    const int E = in_sizes[1];            // 393216

    // 1) per-node partial dot products (tiny)
    {
        const int threads = 256;             // 8 warps/block
        int blocks = (N * 32 + threads - 1) / threads;
        node_partials<<<blocks, threads>>>(h, W, N);
    }

    // 2) fill scores with NEG (the irreducible 604MB DRAM write)
    {
        long long total = (long long)N * N;
        int n4 = (int)(total >> 2);
        const int threads = 256;
        int blocks = (n4 + threads - 1) / threads;
        fill_kernel<<<blocks, threads>>>((float4*)out, n4);
    }

    // 3) scatter edge scores
    {
        const int threads = 256;
        int blocks = (E + threads - 1) / threads;
        scatter_kernel<<<blocks, threads>>>(sources, dests, weights, W, b, out, E, N);
    }
}